// round 15
// baseline (speedup 1.0000x reference)
#include <cuda_runtime.h>
#include <cuda_fp16.h>
#include <mma.h>
#include <cstdint>

using namespace nvcuda;

// v14: v12 (1313us baseline) + two minimal changes:
//  1. all-thread acquire spin replaces (tid0 spin + __syncthreads)  [-1 barrier]
//  2. half=1 mirrors h into SMEM (sHb); prevH (and dH when it aliases h(t-1))
//     read from SMEM -> removes L2 RT from the h-half critical chain.
// Everything else verbatim from the validated v12.

#define TT   256
#define BB   256
#define KD   192
#define RH   256
#define BS   16
#define NG   16

__device__ float g_h2[4][TT][BB][64];
__device__ float g_C2[4][TT][BB][128];
__device__ float g_o2[4][TT][BB][64];
__device__ int   g_hf2[4][NG];
__device__ int   g_of2[4][NG];

__device__ __forceinline__ float sigm(float x){
    return __fdividef(1.f, 1.f + __expf(-x));
}
__device__ __forceinline__ float tanh_f(float x){
    float e = __expf(2.f * x);
    return 1.f - __fdividef(2.f, e + 1.f);
}
__device__ __forceinline__ void st_release(int* p, int v){
    asm volatile("st.release.gpu.global.b32 [%0], %1;" :: "l"(p), "r"(v) : "memory");
}
__device__ __forceinline__ int ld_acquire(const int* p){
    int v;
    asm volatile("ld.acquire.gpu.global.b32 %0, [%1];" : "=r"(v) : "l"(p) : "memory");
    return v;
}

extern "C" __global__ void reset_kernel(){
    int i = threadIdx.x;
    if (i < 4*NG){ ((int*)g_hf2)[i] = 0; ((int*)g_of2)[i] = 0; }
}

extern "C" __global__ void dummy_kernel(){}

// ===================== SMEM layout ===========================================
#define M_AST  200
#define M_BST  200
#define M_GST  20
#define M_AHI  0
#define M_ALO  (M_AHI + RH*M_AST*2)
#define M_BIAS (M_ALO + RH*M_AST*2)
#define M_BHI  (M_BIAS + 1024)
#define M_BLO  (M_BHI + BS*M_BST*2)
#define M_G    M_BHI
#define M_HB   (M_G + RH*M_GST*4)          // h loopback: 16 x 64 fp32 = 4KB
#define M_TOTAL (M_HB + BS*64*4)           // 230400 B

extern "C" __global__ void __launch_bounds__(256,1)
rnn_mma(const float* __restrict__ X, const float* __restrict__ W,
        const float* __restrict__ Bv)
{
    extern __shared__ char smem[];
    __half* sAhi = (__half*)(smem + M_AHI);
    __half* sAlo = (__half*)(smem + M_ALO);
    __half* sBhi = (__half*)(smem + M_BHI);
    __half* sBlo = (__half*)(smem + M_BLO);
    float*  sBia = (float*)(smem + M_BIAS);
    float*  sG   = (float*)(smem + M_G);
    float*  sHb  = (float*)(smem + M_HB);

    const int tid  = threadIdx.x;
    const int wid  = tid >> 5;
    const int bid  = blockIdx.x;
    const int l    = bid >> 5;
    const int half = (bid >> 4) & 1;
    const int g    = bid & 15;
    const int G0   = g * BS;
    const int d    = (l==0) ? 1 : ((l==1) ? 3 : ((l==2) ? 6 : 12));

    const float* Wl = W + (size_t)l * 512 * KD;
    #pragma unroll 4
    for (int it = 0; it < 96; ++it){
        int idx = it*512 + tid*2;
        int r = idx / KD;
        int k = idx - r*KD;
        int grow = ((r>>6)<<7) + (half<<6) + (r&63);
        float2 w = *(const float2*)(Wl + (size_t)grow*KD + k);
        __half hx = __float2half_rn(w.x);
        __half hy = __float2half_rn(w.y);
        float lx = (w.x - __half2float(hx)) * 4096.f;
        float ly = (w.y - __half2float(hy)) * 4096.f;
        *(__half2*)(sAhi + r*M_AST + k) = __halves2half2(hx, hy);
        *(__half2*)(sAlo + r*M_AST + k) =
            __halves2half2(__float2half_rn(lx), __float2half_rn(ly));
    }
    {
        int grow = ((tid>>6)<<7) + (half<<6) + (tid&63);
        sBia[tid] = Bv[l*512 + grow];
    }
    __syncthreads();

    const int eb  = tid >> 4;
    const int es0 = (tid & 15) << 2;
    float cP[4] = {0.f, 0.f, 0.f, 0.f};
    const int m0 = wid * 32;

    for (int t = 0; t < TT; ++t){
        // ---- producer waits: ALL threads spin on acquire loads (no barrier).
        // Safe: B-region writes below are ordered vs last step's B-reads by the
        // iteration-ending __syncthreads; each thread's __ldcg is guarded by
        // its own acquire.
        if (l > 0){
            const int* fp = &g_of2[l-1][g];
            while (ld_acquire(fp) < t+1) {}
        }
        if (half == 0 && t > 0){
            const int* fp = &g_hf2[l][g];
            while (ld_acquire(fp) < t) {}
        }

        // ---- stage xh as fp16 hi/lo (v12 structure; SMEM path for own h) ----
        const float* srcX = (l==0) ? (X + ((size_t)t*BB + G0)*64)
                                   : &g_o2[l-1][t][G0][0];
        const float* srcP = (t > 0)  ? &g_h2[l][t-1][G0][0] : (const float*)0;
        const float* srcD = (t >= d) ? &g_h2[l][t-d][G0][0] : srcP;
        // prevH comes from SMEM when this CTA produced it (half==1)
        const bool pFromS = (half == 1) && (t > 0);
        // dH aliases h(t-1) when d==1 or t<d -> same SMEM path
        const bool dFromS = (half == 1) && (t > 0) && (d == 1 || t < d);
        #pragma unroll
        for (int it = 0; it < 6; ++it){
            int idx = it*512 + tid*2;
            int sec = idx >> 10;
            int rem = idx & 1023;
            int b   = rem >> 6;
            int c   = rem & 63;
            float2 v;
            if (sec == 0){
                v = __ldcg((const float2*)(srcX + b*64 + c));
            } else {
                bool fromS = (sec == 1) ? pFromS : dFromS;
                const float* gp = (sec == 1) ? srcP : srcD;
                if (fromS)   v = *(const float2*)(sHb + b*64 + c);
                else if (gp) v = __ldcg((const float2*)(gp + b*64 + c));
                else         v = make_float2(0.f, 0.f);
            }
            __half hx = __float2half_rn(v.x);
            __half hy = __float2half_rn(v.y);
            float lx = (v.x - __half2float(hx)) * 4096.f;
            float ly = (v.y - __half2float(hy)) * 4096.f;
            int k = sec*64 + c;
            *(__half2*)(sBhi + b*M_BST + k) = __halves2half2(hx, hy);
            *(__half2*)(sBlo + b*M_BST + k) =
                __halves2half2(__float2half_rn(lx), __float2half_rn(ly));
        }
        __syncthreads();

        // ---- WMMA: accH = Whi@xhi ; accL = Whi@xlo + Wlo@xhi ----
        wmma::fragment<wmma::accumulator, 16,16,16, float> accH[2], accL[2];
        #pragma unroll
        for (int mt = 0; mt < 2; ++mt){
            wmma::fill_fragment(accH[mt], 0.f);
            wmma::fill_fragment(accL[mt], 0.f);
        }
        #pragma unroll 2
        for (int kt = 0; kt < 12; ++kt){
            int k0 = kt * 16;
            wmma::fragment<wmma::matrix_b, 16,16,16, __half, wmma::col_major> bH, bL;
            wmma::load_matrix_sync(bH, sBhi + k0, M_BST);
            wmma::load_matrix_sync(bL, sBlo + k0, M_BST);
            #pragma unroll
            for (int mt = 0; mt < 2; ++mt){
                wmma::fragment<wmma::matrix_a, 16,16,16, __half, wmma::row_major> aH, aL;
                wmma::load_matrix_sync(aH, sAhi + (m0 + mt*16)*M_AST + k0, M_AST);
                wmma::load_matrix_sync(aL, sAlo + (m0 + mt*16)*M_AST + k0, M_AST);
                wmma::mma_sync(accH[mt], aH, bH, accH[mt]);
                wmma::mma_sync(accL[mt], aH, bL, accL[mt]);
                wmma::mma_sync(accL[mt], aL, bH, accL[mt]);
            }
        }
        __syncthreads();   // B consumed -> overlay gates onto B region

        {
            const float sc = 2.44140625e-4f;
            #pragma unroll
            for (int mt = 0; mt < 2; ++mt){
                #pragma unroll
                for (int i = 0; i < accH[mt].num_elements; ++i)
                    accH[mt].x[i] = fmaf(accL[mt].x[i], sc, accH[mt].x[i]);
                wmma::store_matrix_sync(sG + (m0 + mt*16)*M_GST, accH[mt], M_GST,
                                        wmma::mem_row_major);
            }
        }
        __syncthreads();

        // ---- gate math: thread = batch eb, states es0..es0+3 (v12 verbatim) --
        {
            float4 b0v = *(const float4*)(sBia +        es0);
            float4 b1v = *(const float4*)(sBia +  64 +  es0);
            float4 b2v = *(const float4*)(sBia + 128 +  es0);
            float4 b3v = *(const float4*)(sBia + 192 +  es0);
            float4 dC = make_float4(0.f, 0.f, 0.f, 0.f);
            if (t >= d) dC = *(const float4*)(&g_C2[l][t-d][G0+eb][(half<<6) + es0]);

            const float* dCp = &dC.x;
            const float* bp0 = &b0v.x; const float* bp1 = &b1v.x;
            const float* bp2 = &b2v.x; const float* bp3 = &b3v.x;
            float nc[4], wh[4];
            #pragma unroll
            for (int i = 0; i < 4; ++i){
                int srow = es0 + i;
                float q0 = sG[(      srow)*M_GST + eb];
                float q1 = sG[( 64 + srow)*M_GST + eb];
                float q2 = sG[(128 + srow)*M_GST + eb];
                float q3 = sG[(192 + srow)*M_GST + eb];
                float f  = sigm(q0 + bp0[i] + 1.f);
                float ns = tanh_f(q1 + bp1[i]);
                float al = sigm(q2 + bp2[i]);
                float oo = sigm(q3 + bp3[i]);
                float wc = (t >= d) ? (al*cP[i] + (1.f-al)*dCp[i]) : cP[i];
                float c2 = (t > 0)  ? (f*wc + (1.f-f)*ns) : ns;
                nc[i] = c2; wh[i] = oo*c2; cP[i] = c2;
            }

            *(float4*)(&g_C2[l][t][G0+eb][(half<<6) + es0]) =
                make_float4(nc[0], nc[1], nc[2], nc[3]);
            float4 whv = make_float4(wh[0], wh[1], wh[2], wh[3]);
            if (half){
                *(float4*)(&g_h2[l][t][G0+eb][es0]) = whv;   // for peer (global)
                *(float4*)(sHb + eb*64 + es0) = whv;         // own loopback (SMEM)
            } else {
                *(float4*)(&g_o2[l][t][G0+eb][es0]) = whv;
            }
        }

        __threadfence();
        __syncthreads();
        if (tid == 0){
            if (half) st_release(&g_hf2[l][g], t + 1);
            else      st_release(&g_of2[l][g], t + 1);
        }
    }
}

// ===================== projection ============================================
extern "C" __global__ void __launch_bounds__(256)
proj_kernel(const float* __restrict__ Wa, const float* __restrict__ ba,
            float* __restrict__ out)
{
    __shared__ float sWa[64*64];
    __shared__ float sba[64];
    for (int i = threadIdx.x; i < 4096; i += 256) sWa[i] = Wa[i];
    if (threadIdx.x < 64) sba[threadIdx.x] = ba[threadIdx.x];
    __syncthreads();

    int row = blockIdx.x * 256 + threadIdx.x;
    const float* p1 = &g_o2[1][0][0][0] + (size_t)row * 64;
    const float* p3 = &g_o2[3][0][0][0] + (size_t)row * 64;
    float v[64];
    #pragma unroll
    for (int i = 0; i < 64; i += 4){
        float4 a = *(const float4*)(p1 + i);
        float4 c = *(const float4*)(p3 + i);
        v[i+0] = a.x + c.x;  v[i+1] = a.y + c.y;
        v[i+2] = a.z + c.z;  v[i+3] = a.w + c.w;
    }
    float* orow = out + (size_t)row * 64;
    for (int j = 0; j < 64; ++j){
        float acc = sba[j];
        const float* wr = sWa + j*64;
        #pragma unroll
        for (int i = 0; i < 64; ++i) acc = fmaf(v[i], wr[i], acc);
        orow[j] = acc;
    }
}

extern "C" void kernel_launch(void* const* d_in, const int* in_sizes, int n_in,
                              void* d_out, int out_size)
{
    const float* x  = (const float*)d_in[0];
    const float* W  = (const float*)d_in[1];
    const float* b  = (const float*)d_in[2];
    const float* Wa = (const float*)d_in[3];
    const float* ba = (const float*)d_in[4];

    cudaFuncSetAttribute((const void*)rnn_mma,
                         cudaFuncAttributeMaxDynamicSharedMemorySize, M_TOTAL);

    reset_kernel<<<1, 64>>>();
    rnn_mma<<<128, 256, M_TOTAL>>>(x, W, b);
    proj_kernel<<<256, 256>>>(Wa, ba, (float*)d_out);
    dummy_kernel<<<1, 32>>>();
}

// round 16
// speedup vs baseline: 1.4004x; 1.4004x over previous
#include <cuda_runtime.h>
#include <cuda_fp16.h>
#include <mma.h>
#include <cstdint>

using namespace nvcuda;

// v15: v12 (1313us, best) restored verbatim + exactly two micro-changes:
//  1. per-step __threadfence() deleted (st.release.gpu + pre-barrier already
//     give the required release ordering)
//  2. dC load hoisted to right after the MMA-consumed barrier so its L2
//     latency overlaps the fragment combine + gate store + barrier.
// Staging loop, spin protocol, epilogue thread mapping: v12 verbatim.

#define TT   256
#define BB   256
#define KD   192
#define RH   256
#define BS   16
#define NG   16

__device__ float g_h2[4][TT][BB][64];
__device__ float g_C2[4][TT][BB][128];
__device__ float g_o2[4][TT][BB][64];
__device__ int   g_hf2[4][NG];
__device__ int   g_of2[4][NG];

__device__ __forceinline__ float sigm(float x){
    return __fdividef(1.f, 1.f + __expf(-x));
}
__device__ __forceinline__ float tanh_f(float x){
    float e = __expf(2.f * x);
    return 1.f - __fdividef(2.f, e + 1.f);
}
__device__ __forceinline__ void st_release(int* p, int v){
    asm volatile("st.release.gpu.global.b32 [%0], %1;" :: "l"(p), "r"(v) : "memory");
}
__device__ __forceinline__ int ld_acquire(const int* p){
    int v;
    asm volatile("ld.acquire.gpu.global.b32 %0, [%1];" : "=r"(v) : "l"(p) : "memory");
    return v;
}

extern "C" __global__ void reset_kernel(){
    int i = threadIdx.x;
    if (i < 4*NG){ ((int*)g_hf2)[i] = 0; ((int*)g_of2)[i] = 0; }
}

extern "C" __global__ void dummy_kernel(){}

// ===================== hardened WMMA rnn =====================================
#define M_AST  200
#define M_BST  200
#define M_GST  20
#define M_AHI  0
#define M_ALO  (M_AHI + RH*M_AST*2)
#define M_BIAS (M_ALO + RH*M_AST*2)
#define M_BHI  (M_BIAS + 1024)
#define M_BLO  (M_BHI + BS*M_BST*2)
#define M_G    M_BHI
#define M_TOTAL (M_G + RH*M_GST*4)

extern "C" __global__ void __launch_bounds__(256,1)
rnn_mma(const float* __restrict__ X, const float* __restrict__ W,
        const float* __restrict__ Bv)
{
    extern __shared__ char smem[];
    __half* sAhi = (__half*)(smem + M_AHI);
    __half* sAlo = (__half*)(smem + M_ALO);
    __half* sBhi = (__half*)(smem + M_BHI);
    __half* sBlo = (__half*)(smem + M_BLO);
    float*  sBia = (float*)(smem + M_BIAS);
    float*  sG   = (float*)(smem + M_G);

    const int tid  = threadIdx.x;
    const int wid  = tid >> 5;
    const int bid  = blockIdx.x;
    const int l    = bid >> 5;
    const int half = (bid >> 4) & 1;
    const int g    = bid & 15;
    const int G0   = g * BS;
    const int d    = (l==0) ? 1 : ((l==1) ? 3 : ((l==2) ? 6 : 12));

    const float* Wl = W + (size_t)l * 512 * KD;
    #pragma unroll 4
    for (int it = 0; it < 96; ++it){
        int idx = it*512 + tid*2;
        int r = idx / KD;
        int k = idx - r*KD;
        int grow = ((r>>6)<<7) + (half<<6) + (r&63);
        float2 w = *(const float2*)(Wl + (size_t)grow*KD + k);
        __half hx = __float2half_rn(w.x);
        __half hy = __float2half_rn(w.y);
        float lx = (w.x - __half2float(hx)) * 4096.f;
        float ly = (w.y - __half2float(hy)) * 4096.f;
        *(__half2*)(sAhi + r*M_AST + k) = __halves2half2(hx, hy);
        *(__half2*)(sAlo + r*M_AST + k) =
            __halves2half2(__float2half_rn(lx), __float2half_rn(ly));
    }
    {
        int grow = ((tid>>6)<<7) + (half<<6) + (tid&63);
        sBia[tid] = Bv[l*512 + grow];
    }
    __syncthreads();

    const int eb  = tid >> 4;
    const int es0 = (tid & 15) << 2;
    float cP[4] = {0.f, 0.f, 0.f, 0.f};
    const int m0 = wid * 32;

    for (int t = 0; t < TT; ++t){
        // ---- hardened producer waits (v12 verbatim) ----
        if (tid == 0){
            if (l > 0){
                const int* fp = &g_of2[l-1][g];
                while (ld_acquire(fp) < t+1) {}
            }
            if (half == 0 && t > 0){
                const int* fp = &g_hf2[l][g];
                while (ld_acquire(fp) < t) {}
            }
        }
        __syncthreads();

        // ---- stage xh as fp16 hi/lo (v12 verbatim) ----
        const float* srcX = (l==0) ? (X + ((size_t)t*BB + G0)*64)
                                   : &g_o2[l-1][t][G0][0];
        const float* srcP = (t > 0)  ? &g_h2[l][t-1][G0][0] : (const float*)0;
        const float* srcD = (t >= d) ? &g_h2[l][t-d][G0][0] : srcP;
        #pragma unroll
        for (int it = 0; it < 6; ++it){
            int idx = it*512 + tid*2;
            int sec = idx >> 10;
            int rem = idx & 1023;
            int b   = rem >> 6;
            int c   = rem & 63;
            const float* s = (sec == 0) ? srcX : ((sec == 1) ? srcP : srcD);
            float2 v = s ? __ldcg((const float2*)(s + b*64 + c))
                         : make_float2(0.f, 0.f);
            __half hx = __float2half_rn(v.x);
            __half hy = __float2half_rn(v.y);
            float lx = (v.x - __half2float(hx)) * 4096.f;
            float ly = (v.y - __half2float(hy)) * 4096.f;
            int k = sec*64 + c;
            *(__half2*)(sBhi + b*M_BST + k) = __halves2half2(hx, hy);
            *(__half2*)(sBlo + b*M_BST + k) =
                __halves2half2(__float2half_rn(lx), __float2half_rn(ly));
        }
        __syncthreads();

        // ---- WMMA: accH = Whi@xhi ; accL = Whi@xlo + Wlo@xhi (v12 verbatim) --
        wmma::fragment<wmma::accumulator, 16,16,16, float> accH[2], accL[2];
        #pragma unroll
        for (int mt = 0; mt < 2; ++mt){
            wmma::fill_fragment(accH[mt], 0.f);
            wmma::fill_fragment(accL[mt], 0.f);
        }
        #pragma unroll 2
        for (int kt = 0; kt < 12; ++kt){
            int k0 = kt * 16;
            wmma::fragment<wmma::matrix_b, 16,16,16, __half, wmma::col_major> bH, bL;
            wmma::load_matrix_sync(bH, sBhi + k0, M_BST);
            wmma::load_matrix_sync(bL, sBlo + k0, M_BST);
            #pragma unroll
            for (int mt = 0; mt < 2; ++mt){
                wmma::fragment<wmma::matrix_a, 16,16,16, __half, wmma::row_major> aH, aL;
                wmma::load_matrix_sync(aH, sAhi + (m0 + mt*16)*M_AST + k0, M_AST);
                wmma::load_matrix_sync(aL, sAlo + (m0 + mt*16)*M_AST + k0, M_AST);
                wmma::mma_sync(accH[mt], aH, bH, accH[mt]);
                wmma::mma_sync(accL[mt], aH, bL, accL[mt]);
                wmma::mma_sync(accL[mt], aL, bH, accL[mt]);
            }
        }
        __syncthreads();   // B consumed -> overlay gates onto B region

        // ---- dC load hoisted here: overlaps combine + gate store + barrier ---
        float4 dC = make_float4(0.f, 0.f, 0.f, 0.f);
        if (t >= d)
            dC = *(const float4*)(&g_C2[l][t-d][G0+eb][(half<<6) + es0]);

        {
            const float sc = 2.44140625e-4f;
            #pragma unroll
            for (int mt = 0; mt < 2; ++mt){
                #pragma unroll
                for (int i = 0; i < accH[mt].num_elements; ++i)
                    accH[mt].x[i] = fmaf(accL[mt].x[i], sc, accH[mt].x[i]);
                wmma::store_matrix_sync(sG + (m0 + mt*16)*M_GST, accH[mt], M_GST,
                                        wmma::mem_row_major);
            }
        }
        __syncthreads();

        // ---- gate math (v12 verbatim, dC already in registers) ----
        {
            float4 b0v = *(const float4*)(sBia +        es0);
            float4 b1v = *(const float4*)(sBia +  64 +  es0);
            float4 b2v = *(const float4*)(sBia + 128 +  es0);
            float4 b3v = *(const float4*)(sBia + 192 +  es0);

            const float* dCp = &dC.x;
            const float* bp0 = &b0v.x; const float* bp1 = &b1v.x;
            const float* bp2 = &b2v.x; const float* bp3 = &b3v.x;
            float nc[4], wh[4];
            #pragma unroll
            for (int i = 0; i < 4; ++i){
                int srow = es0 + i;
                float q0 = sG[(      srow)*M_GST + eb];
                float q1 = sG[( 64 + srow)*M_GST + eb];
                float q2 = sG[(128 + srow)*M_GST + eb];
                float q3 = sG[(192 + srow)*M_GST + eb];
                float f  = sigm(q0 + bp0[i] + 1.f);
                float ns = tanh_f(q1 + bp1[i]);
                float al = sigm(q2 + bp2[i]);
                float oo = sigm(q3 + bp3[i]);
                float wc = (t >= d) ? (al*cP[i] + (1.f-al)*dCp[i]) : cP[i];
                float c2 = (t > 0)  ? (f*wc + (1.f-f)*ns) : ns;
                nc[i] = c2; wh[i] = oo*c2; cP[i] = c2;
            }

            *(float4*)(&g_C2[l][t][G0+eb][(half<<6) + es0]) =
                make_float4(nc[0], nc[1], nc[2], nc[3]);
            float* wdst = half ? &g_h2[l][t][G0+eb][es0] : &g_o2[l][t][G0+eb][es0];
            *(float4*)wdst = make_float4(wh[0], wh[1], wh[2], wh[3]);
        }

        // release: __syncthreads gives intra-CTA happens-before; st.release.gpu
        // publishes with release semantics (threadfence deleted as redundant).
        __syncthreads();
        if (tid == 0){
            if (half) st_release(&g_hf2[l][g], t + 1);
            else      st_release(&g_of2[l][g], t + 1);
        }
    }
}

// ===================== projection ============================================
extern "C" __global__ void __launch_bounds__(256)
proj_kernel(const float* __restrict__ Wa, const float* __restrict__ ba,
            float* __restrict__ out)
{
    __shared__ float sWa[64*64];
    __shared__ float sba[64];
    for (int i = threadIdx.x; i < 4096; i += 256) sWa[i] = Wa[i];
    if (threadIdx.x < 64) sba[threadIdx.x] = ba[threadIdx.x];
    __syncthreads();

    int row = blockIdx.x * 256 + threadIdx.x;
    const float* p1 = &g_o2[1][0][0][0] + (size_t)row * 64;
    const float* p3 = &g_o2[3][0][0][0] + (size_t)row * 64;
    float v[64];
    #pragma unroll
    for (int i = 0; i < 64; i += 4){
        float4 a = *(const float4*)(p1 + i);
        float4 c = *(const float4*)(p3 + i);
        v[i+0] = a.x + c.x;  v[i+1] = a.y + c.y;
        v[i+2] = a.z + c.z;  v[i+3] = a.w + c.w;
    }
    float* orow = out + (size_t)row * 64;
    for (int j = 0; j < 64; ++j){
        float acc = sba[j];
        const float* wr = sWa + j*64;
        #pragma unroll
        for (int i = 0; i < 64; ++i) acc = fmaf(v[i], wr[i], acc);
        orow[j] = acc;
    }
}

extern "C" void kernel_launch(void* const* d_in, const int* in_sizes, int n_in,
                              void* d_out, int out_size)
{
    const float* x  = (const float*)d_in[0];
    const float* W  = (const float*)d_in[1];
    const float* b  = (const float*)d_in[2];
    const float* Wa = (const float*)d_in[3];
    const float* ba = (const float*)d_in[4];

    cudaFuncSetAttribute((const void*)rnn_mma,
                         cudaFuncAttributeMaxDynamicSharedMemorySize, M_TOTAL);

    reset_kernel<<<1, 64>>>();
    rnn_mma<<<128, 256, M_TOTAL>>>(x, W, b);
    proj_kernel<<<256, 256>>>(Wa, ba, (float*)d_out);
    dummy_kernel<<<1, 32>>>();
}